// round 8
// baseline (speedup 1.0000x reference)
#include <cuda_runtime.h>
#include <cuda_bf16.h>
#include <math.h>
#include <stdint.h>

// Problem constants (fixed shapes)
#define BB 4
#define SS 2048
#define DM 1024
#define NH 16
#define HD 64
#define MROWS (BB * SS)   // 8192

// ---------------- scratch (static __device__, no allocation) ----------------
__device__ float g_q[MROWS * DM];
__device__ float g_k[MROWS * DM];
__device__ float g_v[MROWS * DM];
__device__ float g_attn[MROWS * DM];
__device__ float g_beta[MROWS * NH];
__device__ float g_invrms[MROWS];

// bf16 hi/lo split planes
__device__ __nv_bfloat16 g_Whi[4 * DM * DM];
__device__ __nv_bfloat16 g_Wlo[4 * DM * DM];
__device__ __nv_bfloat16 g_xhi[MROWS * DM];
__device__ __nv_bfloat16 g_xlo[MROWS * DM];
__device__ __nv_bfloat16 g_ahi[MROWS * DM];
__device__ __nv_bfloat16 g_alo[MROWS * DM];

// ---------------- bf16 split helper -----------------------------------------
__device__ __forceinline__ void bsplit4(float4 v, uint32_t* hi, uint32_t* lo)
{
    __nv_bfloat162 h01 = __floats2bfloat162_rn(v.x, v.y);
    __nv_bfloat162 h23 = __floats2bfloat162_rn(v.z, v.w);
    float2 f01 = __bfloat1622float2(h01);
    float2 f23 = __bfloat1622float2(h23);
    __nv_bfloat162 l01 = __floats2bfloat162_rn(v.x - f01.x, v.y - f01.y);
    __nv_bfloat162 l23 = __floats2bfloat162_rn(v.z - f23.x, v.w - f23.y);
    hi[0] = *(uint32_t*)&h01; hi[1] = *(uint32_t*)&h23;
    lo[0] = *(uint32_t*)&l01; lo[1] = *(uint32_t*)&l23;
}

// ---------------- one-shot split kernels -------------------------------------
__global__ __launch_bounds__(256)
void split_w_kernel(const float* __restrict__ Wq, const float* __restrict__ Wk,
                    const float* __restrict__ Wv, const float* __restrict__ Wo)
{
    const float* W = (blockIdx.y == 0) ? Wq : (blockIdx.y == 1) ? Wk
                   : (blockIdx.y == 2) ? Wv : Wo;
    size_t i = (size_t)blockIdx.x * 256 + threadIdx.x;    // float4 idx, 262144
    float4 v = ((const float4*)W)[i];
    uint32_t hi[2], lo[2];
    bsplit4(v, hi, lo);
    size_t base = (size_t)blockIdx.y * (DM * DM / 4);
    ((uint2*)g_Whi)[base + i] = make_uint2(hi[0], hi[1]);
    ((uint2*)g_Wlo)[base + i] = make_uint2(lo[0], lo[1]);
}

__global__ __launch_bounds__(256)
void split_x_kernel(const float* __restrict__ x)
{
    size_t i = (size_t)blockIdx.x * 256 + threadIdx.x;    // float4 idx, 2M
    float4 v = ((const float4*)x)[i];
    uint32_t hi[2], lo[2];
    bsplit4(v, hi, lo);
    ((uint2*)g_xhi)[i] = make_uint2(hi[0], hi[1]);
    ((uint2*)g_xlo)[i] = make_uint2(lo[0], lo[1]);
}

// attn * invrms[row] * rmsw[col], then split (fused rmsnorm)
__global__ __launch_bounds__(256)
void split_attn_kernel(const float* __restrict__ rmsw)
{
    size_t i = (size_t)blockIdx.x * 256 + threadIdx.x;    // float4 idx, 2M
    int row = (int)(i >> 8);                              // 256 float4 per row
    int c4 = (int)(i & 255);
    float4 v = ((const float4*)g_attn)[i];
    float s = g_invrms[row];
    float4 w = ((const float4*)rmsw)[c4];
    v.x *= s * w.x; v.y *= s * w.y; v.z *= s * w.z; v.w *= s * w.w;
    uint32_t hi[2], lo[2];
    bsplit4(v, hi, lo);
    ((uint2*)g_ahi)[i] = make_uint2(hi[0], hi[1]);
    ((uint2*)g_alo)[i] = make_uint2(lo[0], lo[1]);
}

// ---------------- tensor-core GEMM: C = epi(A[M,K] @ B[N,K]^T) --------------
// bf16x3 (hi*hi + hi*lo + lo*hi) with pre-split operands. Staging is pure
// LDG.128 -> STS.128. BM=BN=128, BK=16, 256 threads (8 warps: 4M x 2N).

#define RBK 16
#define RBP 24   // padded bf16 row: 48B -> conflict-free frag LDS

__device__ __forceinline__ void mma_bf16(float* c, const uint32_t* a,
                                         uint32_t b0, uint32_t b1)
{
    asm volatile(
        "mma.sync.aligned.m16n8k16.row.col.f32.bf16.bf16.f32 "
        "{%0,%1,%2,%3},{%4,%5,%6,%7},{%8,%9},{%0,%1,%2,%3};"
        : "+f"(c[0]), "+f"(c[1]), "+f"(c[2]), "+f"(c[3])
        : "r"(a[0]), "r"(a[1]), "r"(a[2]), "r"(a[3]), "r"(b0), "r"(b1));
}

// epilogue modes: 0 = none, 1 = silu, 2 = silu + per-64col l2-normalize
__device__ __forceinline__
void mma_gemm_body(const __nv_bfloat16* __restrict__ Ahi,
                   const __nv_bfloat16* __restrict__ Alo,
                   const __nv_bfloat16* __restrict__ Bhi,
                   const __nv_bfloat16* __restrict__ Blo,
                   float* __restrict__ C, int epi_mode)
{
    const int K = DM, N = DM;
    __shared__ __align__(16) __nv_bfloat16 Ah[128][RBP];
    __shared__ __align__(16) __nv_bfloat16 Al[128][RBP];
    __shared__ __align__(16) __nv_bfloat16 Bh[128][RBP];
    __shared__ __align__(16) __nv_bfloat16 Bl[128][RBP];

    const int tid = threadIdx.x;
    const int lane = tid & 31;
    const int warp = tid >> 5;
    const int warp_m = warp & 3;
    const int warp_n = warp >> 2;
    const int g = lane >> 2;
    const int tg = lane & 3;

    const int bm0 = blockIdx.y * 128;
    const int bn0 = blockIdx.x * 128;

    // staging map: thread -> (row, 8-elem half)
    const int srow = tid >> 1;
    const int shalf = (tid & 1) * 8;
    const size_t aoff = (size_t)(bm0 + srow) * K + shalf;
    const size_t boff = (size_t)(bn0 + srow) * K + shalf;

    float acc[2][8][4];
#pragma unroll
    for (int mt = 0; mt < 2; mt++)
#pragma unroll
        for (int nt = 0; nt < 8; nt++)
#pragma unroll
            for (int r = 0; r < 4; r++) acc[mt][nt][r] = 0.f;

    // preload tile 0
    uint4 vah = *(const uint4*)(Ahi + aoff);
    uint4 val = *(const uint4*)(Alo + aoff);
    uint4 vbh = *(const uint4*)(Bhi + boff);
    uint4 vbl = *(const uint4*)(Blo + boff);

    for (int k0 = 0; k0 < K; k0 += RBK) {
        *(uint4*)&Ah[srow][shalf] = vah;
        *(uint4*)&Al[srow][shalf] = val;
        *(uint4*)&Bh[srow][shalf] = vbh;
        *(uint4*)&Bl[srow][shalf] = vbl;
        __syncthreads();

        if (k0 + RBK < K) {
            vah = *(const uint4*)(Ahi + aoff + k0 + RBK);
            val = *(const uint4*)(Alo + aoff + k0 + RBK);
            vbh = *(const uint4*)(Bhi + boff + k0 + RBK);
            vbl = *(const uint4*)(Blo + boff + k0 + RBK);
        }

        uint32_t ah[2][4], al[2][4];
#pragma unroll
        for (int mt = 0; mt < 2; mt++) {
            int mr = warp_m * 32 + mt * 16 + g;
            ah[mt][0] = *(const uint32_t*)&Ah[mr][2 * tg];
            ah[mt][1] = *(const uint32_t*)&Ah[mr + 8][2 * tg];
            ah[mt][2] = *(const uint32_t*)&Ah[mr][8 + 2 * tg];
            ah[mt][3] = *(const uint32_t*)&Ah[mr + 8][8 + 2 * tg];
            al[mt][0] = *(const uint32_t*)&Al[mr][2 * tg];
            al[mt][1] = *(const uint32_t*)&Al[mr + 8][2 * tg];
            al[mt][2] = *(const uint32_t*)&Al[mr][8 + 2 * tg];
            al[mt][3] = *(const uint32_t*)&Al[mr + 8][8 + 2 * tg];
        }
#pragma unroll
        for (int nt = 0; nt < 8; nt++) {
            int nr = warp_n * 64 + nt * 8 + g;
            uint32_t bh0 = *(const uint32_t*)&Bh[nr][2 * tg];
            uint32_t bh1 = *(const uint32_t*)&Bh[nr][8 + 2 * tg];
            uint32_t bl0 = *(const uint32_t*)&Bl[nr][2 * tg];
            uint32_t bl1 = *(const uint32_t*)&Bl[nr][8 + 2 * tg];
#pragma unroll
            for (int mt = 0; mt < 2; mt++) {
                mma_bf16(acc[mt][nt], ah[mt], bh0, bh1);  // hi*hi
                mma_bf16(acc[mt][nt], ah[mt], bl0, bl1);  // hi*lo
                mma_bf16(acc[mt][nt], al[mt], bh0, bh1);  // lo*hi
            }
        }
        __syncthreads();
    }

    // epilogue
    float v[2][8][4];
#pragma unroll
    for (int mt = 0; mt < 2; mt++)
#pragma unroll
        for (int nt = 0; nt < 8; nt++)
#pragma unroll
            for (int r = 0; r < 4; r++) {
                float x = acc[mt][nt][r];
                if (epi_mode >= 1) x = x / (1.f + expf(-x));
                v[mt][nt][r] = x;
            }

    if (epi_mode == 2) {
        // l2-normalize each row's 64-col head segment (whole warp_n half)
#pragma unroll
        for (int mt = 0; mt < 2; mt++) {
            float s0 = 0.f, s1 = 0.f;   // row g, row g+8
#pragma unroll
            for (int nt = 0; nt < 8; nt++) {
                s0 = fmaf(v[mt][nt][0], v[mt][nt][0],
                     fmaf(v[mt][nt][1], v[mt][nt][1], s0));
                s1 = fmaf(v[mt][nt][2], v[mt][nt][2],
                     fmaf(v[mt][nt][3], v[mt][nt][3], s1));
            }
            s0 += __shfl_xor_sync(0xffffffffu, s0, 1);
            s0 += __shfl_xor_sync(0xffffffffu, s0, 2);
            s1 += __shfl_xor_sync(0xffffffffu, s1, 1);
            s1 += __shfl_xor_sync(0xffffffffu, s1, 2);
            float i0 = 1.f / (sqrtf(s0) + 1e-6f);
            float i1 = 1.f / (sqrtf(s1) + 1e-6f);
#pragma unroll
            for (int nt = 0; nt < 8; nt++) {
                v[mt][nt][0] *= i0; v[mt][nt][1] *= i0;
                v[mt][nt][2] *= i1; v[mt][nt][3] *= i1;
            }
        }
    }

#pragma unroll
    for (int mt = 0; mt < 2; mt++)
#pragma unroll
        for (int nt = 0; nt < 8; nt++) {
            int row0 = bm0 + warp_m * 32 + mt * 16 + g;
            int cb = bn0 + warp_n * 64 + nt * 8 + 2 * tg;
            *(float2*)(C + (size_t)row0 * N + cb)       = make_float2(v[mt][nt][0], v[mt][nt][1]);
            *(float2*)(C + (size_t)(row0 + 8) * N + cb) = make_float2(v[mt][nt][2], v[mt][nt][3]);
        }
}

// Fused QKV: blockIdx.z selects (Wq->g_q silu+l2, Wk->g_k silu+l2, Wv->g_v silu)
__global__ __launch_bounds__(256, 2)
void mma_qkv()
{
    const size_t wb = (size_t)blockIdx.z * DM * DM;
    if (blockIdx.z == 0)      mma_gemm_body(g_xhi, g_xlo, g_Whi + wb, g_Wlo + wb, g_q, 2);
    else if (blockIdx.z == 1) mma_gemm_body(g_xhi, g_xlo, g_Whi + wb, g_Wlo + wb, g_k, 2);
    else                      mma_gemm_body(g_xhi, g_xlo, g_Whi + wb, g_Wlo + wb, g_v, 1);
}

// Output projection: (pre-scaled attn) @ Wo^T -> out
__global__ __launch_bounds__(256, 2)
void mma_o(float* __restrict__ outp)
{
    const size_t wb = (size_t)3 * DM * DM;
    mma_gemm_body(g_ahi, g_alo, g_Whi + wb, g_Wlo + wb, outp, 0);
}

// ---------------- beta: sigmoid(x @ Wbeta^T), (8192,16) ---------------------
__global__ __launch_bounds__(512)
void beta_kernel(const float* __restrict__ x, const float* __restrict__ Wb)
{
    __shared__ __align__(16) float sx[DM];
    const int row = blockIdx.x;
    const int tid = threadIdx.x;
    {
        float2 t = *(const float2*)(x + (size_t)row * DM + 2 * tid);
        *(float2*)(sx + 2 * tid) = t;
    }
    __syncthreads();
    const int w = tid >> 5, l = tid & 31;   // warp w -> head w (16 warps)
    const float* wrow = Wb + (size_t)w * DM;
    float s = 0.f;
#pragma unroll
    for (int i = 0; i < 8; i++) {
        int kb = i * 128 + l * 4;
        float4 wv = *(const float4*)(wrow + kb);
        float4 xv = *(const float4*)(sx + kb);
        s += wv.x * xv.x + wv.y * xv.y + wv.z * xv.z + wv.w * xv.w;
    }
#pragma unroll
    for (int o = 16; o; o >>= 1) s += __shfl_xor_sync(0xffffffffu, s, o);
    if (l == 0) g_beta[(size_t)row * NH + w] = 1.f / (1.f + expf(-s));
}

// ---------------- per-row inverse RMS ----------------------------------------
__global__ __launch_bounds__(256)
void row_rms_kernel()
{
    __shared__ float red[8];
    const int row = blockIdx.x;
    const int tid = threadIdx.x;
    const int l = tid & 31, wd = tid >> 5;
    float4 x = ((const float4*)(g_attn + (size_t)row * DM))[tid];
    float s = x.x * x.x + x.y * x.y + x.z * x.z + x.w * x.w;
#pragma unroll
    for (int o = 16; o; o >>= 1) s += __shfl_xor_sync(0xffffffffu, s, o);
    if (l == 0) red[wd] = s;
    __syncthreads();
    if (tid == 0) {
        float t = red[0] + red[1] + red[2] + red[3] + red[4] + red[5] + red[6] + red[7];
        g_invrms[row] = rsqrtf(t * (1.f / DM) + 1e-6f);
    }
}

// ---------------- delta-rule recurrence -------------------------------------
// One CTA per (b, head). 256 threads: thread = (col = tid>>2, sub = tid&3).
// M (64x64) kept twice in registers as 16-element segments:
//   C[i] = M[sub*16+i][col]  (column copy)   R[i] = M[col][sub*16+i] (row copy)
// ONE barrier per step: 4-deep stage ring + double-buffered sdelta.
// 3-step-ahead prefetch covers DRAM latency.
__global__ __launch_bounds__(256, 1)
void recurrence_kernel()
{
    const int b = blockIdx.x >> 4;
    const int n = blockIdx.x & 15;
    const int tid = threadIdx.x;
    const int col = tid >> 2;
    const int sub = tid & 3;
    const int r0 = sub * 16;
    const int wid = tid >> 5, lane = tid & 31;

    __shared__ __align__(16) float stage[4][224]; // q[0:64) k[64:128) v[128:192) beta[192]
    __shared__ __align__(16) float sdelta[2][64];

    float C[16], R[16];
#pragma unroll
    for (int i = 0; i < 16; i++) { C[i] = 0.f; R[i] = 0.f; }

    const size_t base0 = ((size_t)(b * SS) * NH + n) * HD;  // step stride = 1024
    const size_t bbase = (size_t)(b * SS) * NH + n;          // beta step stride = 16

    // preload steps 0..2 into slots 0..2
    if (wid < 3) {
        const float* src = (wid == 0) ? g_q : (wid == 1) ? g_k : g_v;
        const int off = wid * 64;
        for (int j = 0; j < 3; j++) {
            float2 t = *(const float2*)(src + base0 + (size_t)j * (NH * HD) + 2 * lane);
            *(float2*)&stage[j][off + 2 * lane] = t;
        }
    } else if (wid == 3 && lane < 3) {
        stage[lane][192] = g_beta[bbase + (size_t)lane * NH];
    }
    __syncthreads();

    for (int s = 0; s < SS; s++) {
        const int slot = s & 3;
        const int sd = s & 1;

        // prefetch step s+3 into registers (committed in phase B)
        float2 pre = make_float2(0.f, 0.f);
        float preb = 0.f;
        const bool has = (s + 3 < SS);
        if (has) {
            size_t o2 = base0 + (size_t)(s + 3) * (NH * HD);
            if (wid == 0) pre = *(const float2*)(g_q + o2 + 2 * lane);
            else if (wid == 1) pre = *(const float2*)(g_k + o2 + 2 * lane);
            else if (wid == 2) pre = *(const float2*)(g_v + o2 + 2 * lane);
            else if (wid == 3 && lane == 0) preb = g_beta[bbase + (size_t)(s + 3) * NH];
        }

        // ---- phase A: dotR = R.k, outp = q.C (both on pre-update M) ----
        float kseg[16], qseg[16];
#pragma unroll
        for (int j = 0; j < 4; j++) {
            *(float4*)&kseg[4 * j] = *(const float4*)&stage[slot][64 + r0 + 4 * j];
            *(float4*)&qseg[4 * j] = *(const float4*)&stage[slot][r0 + 4 * j];
        }
        float d0 = 0.f, d1 = 0.f, d2 = 0.f, d3 = 0.f;
        float e0 = 0.f, e1 = 0.f, e2 = 0.f, e3 = 0.f;
#pragma unroll
        for (int j = 0; j < 4; j++) {
            d0 = fmaf(R[4*j],   kseg[4*j],   d0);
            d1 = fmaf(R[4*j+1], kseg[4*j+1], d1);
            d2 = fmaf(R[4*j+2], kseg[4*j+2], d2);
            d3 = fmaf(R[4*j+3], kseg[4*j+3], d3);
            e0 = fmaf(qseg[4*j],   C[4*j],   e0);
            e1 = fmaf(qseg[4*j+1], C[4*j+1], e1);
            e2 = fmaf(qseg[4*j+2], C[4*j+2], e2);
            e3 = fmaf(qseg[4*j+3], C[4*j+3], e3);
        }
        float dotR = (d0 + d1) + (d2 + d3);
        float outp = (e0 + e1) + (e2 + e3);
        dotR += __shfl_xor_sync(0xffffffffu, dotR, 1);
        outp += __shfl_xor_sync(0xffffffffu, outp, 1);
        dotR += __shfl_xor_sync(0xffffffffu, dotR, 2);
        outp += __shfl_xor_sync(0xffffffffu, outp, 2);

        const float vcol = stage[slot][128 + col];
        const float kcol = stage[slot][64 + col];
        const float bs   = stage[slot][192];
        const float delta = vcol - dotR;
        if (sub == 0) sdelta[sd][col] = delta;
        if (sub == 1) g_attn[base0 + (size_t)s * (NH * HD) + col] = outp;
        __syncthreads();

        // ---- phase B: rank-1 updates + prefetch commit ----
        const float bd = bs * delta;     // own-column delta from register
        const float bk = bs * kcol;
        float dseg[16];
#pragma unroll
        for (int j = 0; j < 4; j++)
            *(float4*)&dseg[4 * j] = *(const float4*)&sdelta[sd][r0 + 4 * j];
#pragma unroll
        for (int i = 0; i < 16; i++) {
            C[i] = fmaf(bd, kseg[i], C[i]);
            R[i] = fmaf(bk, dseg[i], R[i]);
        }

        if (has) {
            const int ws = (s + 3) & 3;
            if (wid == 0) *(float2*)&stage[ws][2 * lane] = pre;
            else if (wid == 1) *(float2*)&stage[ws][64 + 2 * lane] = pre;
            else if (wid == 2) *(float2*)&stage[ws][128 + 2 * lane] = pre;
            else if (wid == 3 && lane == 0) stage[ws][192] = preb;
        }
        // no second barrier: next phase A touches slot (s+1)&3 and sdelta[sd^1],
        // both >=1 barrier away from their writers.
    }
}

// ---------------- launch (pure kernel launches, no runtime API) -------------
extern "C" void kernel_launch(void* const* d_in, const int* in_sizes, int n_in,
                              void* d_out, int out_size)
{
    const float* x    = (const float*)d_in[0];
    const float* Wq   = (const float*)d_in[1];
    const float* Wk   = (const float*)d_in[2];
    const float* Wv   = (const float*)d_in[3];
    const float* Wo   = (const float*)d_in[4];
    const float* Wb   = (const float*)d_in[5];
    const float* rmsw = (const float*)d_in[6];
    float* outp = (float*)d_out;

    // one-shot bf16 hi/lo splits
    split_w_kernel<<<dim3(DM * DM / 4 / 256, 4), 256>>>(Wq, Wk, Wv, Wo);
    split_x_kernel<<<MROWS * DM / 4 / 256, 256>>>(x);

    // projections: fused SiLU + l2norm(q,k) on tensor cores (bf16x3)
    mma_qkv<<<dim3(DM / 128, MROWS / 128, 3), 256>>>();
    beta_kernel<<<MROWS, 512>>>(x, Wb);

    // sequential delta-rule recurrence (64 independent states)
    recurrence_kernel<<<BB * NH, 256>>>();

    // rmsnorm fused into attn split, then output projection
    row_rms_kernel<<<MROWS, 256>>>();
    split_attn_kernel<<<MROWS * DM / 4 / 256, 256>>>(rmsw);
    mma_o<<<dim3(DM / 128, MROWS / 128), 256>>>(outp);
}

// round 11
// speedup vs baseline: 1.0638x; 1.0638x over previous
#include <cuda_runtime.h>
#include <cuda_bf16.h>
#include <math.h>
#include <stdint.h>

// Problem constants (fixed shapes)
#define BB 4
#define SS 2048
#define DM 1024
#define NH 16
#define HD 64
#define MROWS (BB * SS)   // 8192

// ---------------- scratch (static __device__, no allocation) ----------------
__device__ float g_q[MROWS * DM];
__device__ float g_k[MROWS * DM];
__device__ float g_v[MROWS * DM];
__device__ float g_attn[MROWS * DM];
__device__ float g_beta[MROWS * NH];
__device__ float g_invrms[MROWS];

// bf16 hi/lo split planes
__device__ __nv_bfloat16 g_Whi[4 * DM * DM];
__device__ __nv_bfloat16 g_Wlo[4 * DM * DM];
__device__ __nv_bfloat16 g_xhi[MROWS * DM];
__device__ __nv_bfloat16 g_xlo[MROWS * DM];
__device__ __nv_bfloat16 g_ahi[MROWS * DM];
__device__ __nv_bfloat16 g_alo[MROWS * DM];

// ---------------- bf16 split helper -----------------------------------------
__device__ __forceinline__ void bsplit4(float4 v, uint32_t* hi, uint32_t* lo)
{
    __nv_bfloat162 h01 = __floats2bfloat162_rn(v.x, v.y);
    __nv_bfloat162 h23 = __floats2bfloat162_rn(v.z, v.w);
    float2 f01 = __bfloat1622float2(h01);
    float2 f23 = __bfloat1622float2(h23);
    __nv_bfloat162 l01 = __floats2bfloat162_rn(v.x - f01.x, v.y - f01.y);
    __nv_bfloat162 l23 = __floats2bfloat162_rn(v.z - f23.x, v.w - f23.y);
    hi[0] = *(uint32_t*)&h01; hi[1] = *(uint32_t*)&h23;
    lo[0] = *(uint32_t*)&l01; lo[1] = *(uint32_t*)&l23;
}

// ---------------- one-shot split kernels -------------------------------------
__global__ __launch_bounds__(256)
void split_w_kernel(const float* __restrict__ Wq, const float* __restrict__ Wk,
                    const float* __restrict__ Wv, const float* __restrict__ Wo)
{
    const float* W = (blockIdx.y == 0) ? Wq : (blockIdx.y == 1) ? Wk
                   : (blockIdx.y == 2) ? Wv : Wo;
    size_t i = (size_t)blockIdx.x * 256 + threadIdx.x;    // float4 idx, 262144
    float4 v = ((const float4*)W)[i];
    uint32_t hi[2], lo[2];
    bsplit4(v, hi, lo);
    size_t base = (size_t)blockIdx.y * (DM * DM / 4);
    ((uint2*)g_Whi)[base + i] = make_uint2(hi[0], hi[1]);
    ((uint2*)g_Wlo)[base + i] = make_uint2(lo[0], lo[1]);
}

__global__ __launch_bounds__(256)
void split_x_kernel(const float* __restrict__ x)
{
    size_t i = (size_t)blockIdx.x * 256 + threadIdx.x;    // float4 idx, 2M
    float4 v = ((const float4*)x)[i];
    uint32_t hi[2], lo[2];
    bsplit4(v, hi, lo);
    ((uint2*)g_xhi)[i] = make_uint2(hi[0], hi[1]);
    ((uint2*)g_xlo)[i] = make_uint2(lo[0], lo[1]);
}

// attn * invrms[row] * rmsw[col], then split (fused rmsnorm)
__global__ __launch_bounds__(256)
void split_attn_kernel(const float* __restrict__ rmsw)
{
    size_t i = (size_t)blockIdx.x * 256 + threadIdx.x;    // float4 idx, 2M
    int row = (int)(i >> 8);                              // 256 float4 per row
    int c4 = (int)(i & 255);
    float4 v = ((const float4*)g_attn)[i];
    float s = g_invrms[row];
    float4 w = ((const float4*)rmsw)[c4];
    v.x *= s * w.x; v.y *= s * w.y; v.z *= s * w.z; v.w *= s * w.w;
    uint32_t hi[2], lo[2];
    bsplit4(v, hi, lo);
    ((uint2*)g_ahi)[i] = make_uint2(hi[0], hi[1]);
    ((uint2*)g_alo)[i] = make_uint2(lo[0], lo[1]);
}

// ---------------- tensor-core GEMM: C = epi(A[M,K] @ B[N,K]^T) --------------
// bf16x3 (hi*hi + hi*lo + lo*hi) with pre-split operands. Staging is pure
// LDG.128 -> STS.128. BM=BN=128, BK=16, 256 threads (8 warps: 4M x 2N).

#define RBK 16
#define RBP 24   // padded bf16 row: 48B -> conflict-free frag LDS

__device__ __forceinline__ void mma_bf16(float* c, const uint32_t* a,
                                         uint32_t b0, uint32_t b1)
{
    asm volatile(
        "mma.sync.aligned.m16n8k16.row.col.f32.bf16.bf16.f32 "
        "{%0,%1,%2,%3},{%4,%5,%6,%7},{%8,%9},{%0,%1,%2,%3};"
        : "+f"(c[0]), "+f"(c[1]), "+f"(c[2]), "+f"(c[3])
        : "r"(a[0]), "r"(a[1]), "r"(a[2]), "r"(a[3]), "r"(b0), "r"(b1));
}

// epilogue modes: 0 = none, 1 = silu, 2 = silu + per-64col l2-normalize
__device__ __forceinline__
void mma_gemm_body(const __nv_bfloat16* __restrict__ Ahi,
                   const __nv_bfloat16* __restrict__ Alo,
                   const __nv_bfloat16* __restrict__ Bhi,
                   const __nv_bfloat16* __restrict__ Blo,
                   float* __restrict__ C, int epi_mode)
{
    const int K = DM, N = DM;
    __shared__ __align__(16) __nv_bfloat16 Ah[128][RBP];
    __shared__ __align__(16) __nv_bfloat16 Al[128][RBP];
    __shared__ __align__(16) __nv_bfloat16 Bh[128][RBP];
    __shared__ __align__(16) __nv_bfloat16 Bl[128][RBP];

    const int tid = threadIdx.x;
    const int lane = tid & 31;
    const int warp = tid >> 5;
    const int warp_m = warp & 3;
    const int warp_n = warp >> 2;
    const int g = lane >> 2;
    const int tg = lane & 3;

    const int bm0 = blockIdx.y * 128;
    const int bn0 = blockIdx.x * 128;

    // staging map: thread -> (row, 8-elem half)
    const int srow = tid >> 1;
    const int shalf = (tid & 1) * 8;
    const size_t aoff = (size_t)(bm0 + srow) * K + shalf;
    const size_t boff = (size_t)(bn0 + srow) * K + shalf;

    float acc[2][8][4];
#pragma unroll
    for (int mt = 0; mt < 2; mt++)
#pragma unroll
        for (int nt = 0; nt < 8; nt++)
#pragma unroll
            for (int r = 0; r < 4; r++) acc[mt][nt][r] = 0.f;

    // preload tile 0
    uint4 vah = *(const uint4*)(Ahi + aoff);
    uint4 val = *(const uint4*)(Alo + aoff);
    uint4 vbh = *(const uint4*)(Bhi + boff);
    uint4 vbl = *(const uint4*)(Blo + boff);

    for (int k0 = 0; k0 < K; k0 += RBK) {
        *(uint4*)&Ah[srow][shalf] = vah;
        *(uint4*)&Al[srow][shalf] = val;
        *(uint4*)&Bh[srow][shalf] = vbh;
        *(uint4*)&Bl[srow][shalf] = vbl;
        __syncthreads();

        if (k0 + RBK < K) {
            vah = *(const uint4*)(Ahi + aoff + k0 + RBK);
            val = *(const uint4*)(Alo + aoff + k0 + RBK);
            vbh = *(const uint4*)(Bhi + boff + k0 + RBK);
            vbl = *(const uint4*)(Blo + boff + k0 + RBK);
        }

        uint32_t ah[2][4], al[2][4];
#pragma unroll
        for (int mt = 0; mt < 2; mt++) {
            int mr = warp_m * 32 + mt * 16 + g;
            ah[mt][0] = *(const uint32_t*)&Ah[mr][2 * tg];
            ah[mt][1] = *(const uint32_t*)&Ah[mr + 8][2 * tg];
            ah[mt][2] = *(const uint32_t*)&Ah[mr][8 + 2 * tg];
            ah[mt][3] = *(const uint32_t*)&Ah[mr + 8][8 + 2 * tg];
            al[mt][0] = *(const uint32_t*)&Al[mr][2 * tg];
            al[mt][1] = *(const uint32_t*)&Al[mr + 8][2 * tg];
            al[mt][2] = *(const uint32_t*)&Al[mr][8 + 2 * tg];
            al[mt][3] = *(const uint32_t*)&Al[mr + 8][8 + 2 * tg];
        }
#pragma unroll
        for (int nt = 0; nt < 8; nt++) {
            int nr = warp_n * 64 + nt * 8 + g;
            uint32_t bh0 = *(const uint32_t*)&Bh[nr][2 * tg];
            uint32_t bh1 = *(const uint32_t*)&Bh[nr][8 + 2 * tg];
            uint32_t bl0 = *(const uint32_t*)&Bl[nr][2 * tg];
            uint32_t bl1 = *(const uint32_t*)&Bl[nr][8 + 2 * tg];
#pragma unroll
            for (int mt = 0; mt < 2; mt++) {
                mma_bf16(acc[mt][nt], ah[mt], bh0, bh1);  // hi*hi
                mma_bf16(acc[mt][nt], ah[mt], bl0, bl1);  // hi*lo
                mma_bf16(acc[mt][nt], al[mt], bh0, bh1);  // lo*hi
            }
        }
        __syncthreads();
    }

    // epilogue
    float v[2][8][4];
#pragma unroll
    for (int mt = 0; mt < 2; mt++)
#pragma unroll
        for (int nt = 0; nt < 8; nt++)
#pragma unroll
            for (int r = 0; r < 4; r++) {
                float x = acc[mt][nt][r];
                if (epi_mode >= 1) x = x / (1.f + expf(-x));
                v[mt][nt][r] = x;
            }

    if (epi_mode == 2) {
        // l2-normalize each row's 64-col head segment (whole warp_n half)
#pragma unroll
        for (int mt = 0; mt < 2; mt++) {
            float s0 = 0.f, s1 = 0.f;   // row g, row g+8
#pragma unroll
            for (int nt = 0; nt < 8; nt++) {
                s0 = fmaf(v[mt][nt][0], v[mt][nt][0],
                     fmaf(v[mt][nt][1], v[mt][nt][1], s0));
                s1 = fmaf(v[mt][nt][2], v[mt][nt][2],
                     fmaf(v[mt][nt][3], v[mt][nt][3], s1));
            }
            s0 += __shfl_xor_sync(0xffffffffu, s0, 1);
            s0 += __shfl_xor_sync(0xffffffffu, s0, 2);
            s1 += __shfl_xor_sync(0xffffffffu, s1, 1);
            s1 += __shfl_xor_sync(0xffffffffu, s1, 2);
            float i0 = 1.f / (sqrtf(s0) + 1e-6f);
            float i1 = 1.f / (sqrtf(s1) + 1e-6f);
#pragma unroll
            for (int nt = 0; nt < 8; nt++) {
                v[mt][nt][0] *= i0; v[mt][nt][1] *= i0;
                v[mt][nt][2] *= i1; v[mt][nt][3] *= i1;
            }
        }
    }

#pragma unroll
    for (int mt = 0; mt < 2; mt++)
#pragma unroll
        for (int nt = 0; nt < 8; nt++) {
            int row0 = bm0 + warp_m * 32 + mt * 16 + g;
            int cb = bn0 + warp_n * 64 + nt * 8 + 2 * tg;
            *(float2*)(C + (size_t)row0 * N + cb)       = make_float2(v[mt][nt][0], v[mt][nt][1]);
            *(float2*)(C + (size_t)(row0 + 8) * N + cb) = make_float2(v[mt][nt][2], v[mt][nt][3]);
        }
}

// Fused QKV: blockIdx.z selects (Wq->g_q silu+l2, Wk->g_k silu+l2, Wv->g_v silu)
__global__ __launch_bounds__(256, 2)
void mma_qkv()
{
    const size_t wb = (size_t)blockIdx.z * DM * DM;
    if (blockIdx.z == 0)      mma_gemm_body(g_xhi, g_xlo, g_Whi + wb, g_Wlo + wb, g_q, 2);
    else if (blockIdx.z == 1) mma_gemm_body(g_xhi, g_xlo, g_Whi + wb, g_Wlo + wb, g_k, 2);
    else                      mma_gemm_body(g_xhi, g_xlo, g_Whi + wb, g_Wlo + wb, g_v, 1);
}

// Output projection: (pre-scaled attn) @ Wo^T -> out
__global__ __launch_bounds__(256, 2)
void mma_o(float* __restrict__ outp)
{
    const size_t wb = (size_t)3 * DM * DM;
    mma_gemm_body(g_ahi, g_alo, g_Whi + wb, g_Wlo + wb, outp, 0);
}

// ---------------- beta: sigmoid(x @ Wbeta^T), (8192,16) ---------------------
__global__ __launch_bounds__(512)
void beta_kernel(const float* __restrict__ x, const float* __restrict__ Wb)
{
    __shared__ __align__(16) float sx[DM];
    const int row = blockIdx.x;
    const int tid = threadIdx.x;
    {
        float2 t = *(const float2*)(x + (size_t)row * DM + 2 * tid);
        *(float2*)(sx + 2 * tid) = t;
    }
    __syncthreads();
    const int w = tid >> 5, l = tid & 31;   // warp w -> head w (16 warps)
    const float* wrow = Wb + (size_t)w * DM;
    float s = 0.f;
#pragma unroll
    for (int i = 0; i < 8; i++) {
        int kb = i * 128 + l * 4;
        float4 wv = *(const float4*)(wrow + kb);
        float4 xv = *(const float4*)(sx + kb);
        s += wv.x * xv.x + wv.y * xv.y + wv.z * xv.z + wv.w * xv.w;
    }
#pragma unroll
    for (int o = 16; o; o >>= 1) s += __shfl_xor_sync(0xffffffffu, s, o);
    if (l == 0) g_beta[(size_t)row * NH + w] = 1.f / (1.f + expf(-s));
}

// ---------------- per-row inverse RMS ----------------------------------------
__global__ __launch_bounds__(256)
void row_rms_kernel()
{
    __shared__ float red[8];
    const int row = blockIdx.x;
    const int tid = threadIdx.x;
    const int l = tid & 31, wd = tid >> 5;
    float4 x = ((const float4*)(g_attn + (size_t)row * DM))[tid];
    float s = x.x * x.x + x.y * x.y + x.z * x.z + x.w * x.w;
#pragma unroll
    for (int o = 16; o; o >>= 1) s += __shfl_xor_sync(0xffffffffu, s, o);
    if (l == 0) red[wd] = s;
    __syncthreads();
    if (tid == 0) {
        float t = red[0] + red[1] + red[2] + red[3] + red[4] + red[5] + red[6] + red[7];
        g_invrms[row] = rsqrtf(t * (1.f / DM) + 1e-6f);
    }
}

// ---------------- delta-rule recurrence -------------------------------------
// One CTA per (b, head). 256 threads: thread = (col = tid>>2, sub = tid&3).
// M (64x64) kept twice in registers as 16-element segments:
//   C[i] = M[sub*16+i][col]  (column copy)   R[i] = M[col][sub*16+i] (row copy)
// Register-pipelined prefetch, unrolled x3 so buffer indices are static:
//   step s ISSUES the LDG for step s+3 into buf[s%3], and COMMITS
//   buf[(s+1)%3] (fetched at step s-2) into stage slot (s+1)&3.
// Issue->commit distance = 2 full step bodies -> LDG latency covered; the
// commit STS no longer exposes a long_scoreboard stall every step.
__global__ __launch_bounds__(256, 1)
void recurrence_kernel()
{
    const int b = blockIdx.x >> 4;
    const int n = blockIdx.x & 15;
    const int tid = threadIdx.x;
    const int col = tid >> 2;
    const int sub = tid & 3;
    const int r0 = sub * 16;
    const int wid = tid >> 5, lane = tid & 31;

    __shared__ __align__(16) float stage[4][224]; // q[0:64) k[64:128) v[128:192) beta[192]
    __shared__ __align__(16) float sdelta[2][64];

    float C[16], R[16];
#pragma unroll
    for (int i = 0; i < 16; i++) { C[i] = 0.f; R[i] = 0.f; }

    const size_t base0 = ((size_t)(b * SS) * NH + n) * HD;  // step stride = 1024
    const size_t bbase = (size_t)(b * SS) * NH + n;          // beta step stride = 16

    const float* vecsrc = (wid == 0) ? g_q : (wid == 1) ? g_k : g_v;
    const int vecoff = wid * 64;

    // prologue: load steps 0..2 into slots 0..2 synchronously (one-time cost)
    if (wid < 3) {
        for (int j = 0; j < 3; j++)
            *(float2*)&stage[j][vecoff + 2 * lane] =
                *(const float2*)(vecsrc + base0 + (size_t)j * (NH * HD) + 2 * lane);
    } else if (wid == 3 && lane < 3) {
        stage[lane][192] = g_beta[bbase + (size_t)lane * NH];
    }
    __syncthreads();

    float2 p0 = make_float2(0.f, 0.f), p1 = p0, p2 = p0;
    float pb0 = 0.f, pb1 = 0.f, pb2 = 0.f;

    auto body = [&](int s, float2& fb, float& fbb, float2& cbv, float& cbb) {
        const int slot = s & 3;
        const int sd = s & 1;

        // issue prefetch for step s+3 (consumed 2 steps later)
        if (s + 3 < SS) {
            if (wid < 3)
                fb = *(const float2*)(vecsrc + base0 + (size_t)(s + 3) * (NH * HD) + 2 * lane);
            else if (wid == 3 && lane == 0)
                fbb = g_beta[bbase + (size_t)(s + 3) * NH];
        }

        // ---- phase A: dotR = R.k, outp = q.C (both on pre-update M) ----
        float kseg[16], qseg[16];
#pragma unroll
        for (int j = 0; j < 4; j++) {
            *(float4*)&kseg[4 * j] = *(const float4*)&stage[slot][64 + r0 + 4 * j];
            *(float4*)&qseg[4 * j] = *(const float4*)&stage[slot][r0 + 4 * j];
        }
        float d0 = 0.f, d1 = 0.f, d2 = 0.f, d3 = 0.f;
        float e0 = 0.f, e1 = 0.f, e2 = 0.f, e3 = 0.f;
#pragma unroll
        for (int j = 0; j < 4; j++) {
            d0 = fmaf(R[4*j],   kseg[4*j],   d0);
            d1 = fmaf(R[4*j+1], kseg[4*j+1], d1);
            d2 = fmaf(R[4*j+2], kseg[4*j+2], d2);
            d3 = fmaf(R[4*j+3], kseg[4*j+3], d3);
            e0 = fmaf(qseg[4*j],   C[4*j],   e0);
            e1 = fmaf(qseg[4*j+1], C[4*j+1], e1);
            e2 = fmaf(qseg[4*j+2], C[4*j+2], e2);
            e3 = fmaf(qseg[4*j+3], C[4*j+3], e3);
        }
        float dotR = (d0 + d1) + (d2 + d3);
        float outp = (e0 + e1) + (e2 + e3);
        dotR += __shfl_xor_sync(0xffffffffu, dotR, 1);
        outp += __shfl_xor_sync(0xffffffffu, outp, 1);
        dotR += __shfl_xor_sync(0xffffffffu, dotR, 2);
        outp += __shfl_xor_sync(0xffffffffu, outp, 2);

        const float vcol = stage[slot][128 + col];
        const float kcol = stage[slot][64 + col];
        const float bs   = stage[slot][192];
        const float delta = vcol - dotR;
        if (sub == 0) sdelta[sd][col] = delta;
        if (sub == 1) g_attn[base0 + (size_t)s * (NH * HD) + col] = outp;

        // commit buffer fetched 2 steps ago -> slot for step s+1
        if (s >= 2 && s + 1 < SS) {
            const int cs = (s + 1) & 3;
            if (wid < 3) *(float2*)&stage[cs][vecoff + 2 * lane] = cbv;
            else if (wid == 3 && lane == 0) stage[cs][192] = cbb;
        }
        __syncthreads();

        // ---- phase B: rank-1 updates (registers from phase A) ----
        const float bd = bs * delta;
        const float bk = bs * kcol;
        float dseg[16];
#pragma unroll
        for (int j = 0; j < 4; j++)
            *(float4*)&dseg[4 * j] = *(const float4*)&sdelta[sd][r0 + 4 * j];
#pragma unroll
        for (int i = 0; i < 16; i++) {
            C[i] = fmaf(bd, kseg[i], C[i]);
            R[i] = fmaf(bk, dseg[i], R[i]);
        }
        // next phase A reads slot (s+1)&3 (committed + barrier-visible) and
        // writes sdelta[sd^1]; readers of sdelta[sd] were pre-next-barrier.
    };

    // main loop unrolled x3 so pipeline buffers have static indices
    for (int s = 0; s < SS - 2; s += 3) {
        body(s,     p0, pb0, p1, pb1);
        body(s + 1, p1, pb1, p2, pb2);
        body(s + 2, p2, pb2, p0, pb0);
    }
    body(SS - 2, p0, pb0, p1, pb1);   // s = 2046 (commits step 2047 from p1)
    body(SS - 1, p1, pb1, p2, pb2);   // s = 2047 (no fetch, no commit)
}

// ---------------- launch (pure kernel launches, no runtime API) -------------
extern "C" void kernel_launch(void* const* d_in, const int* in_sizes, int n_in,
                              void* d_out, int out_size)
{
    const float* x    = (const float*)d_in[0];
    const float* Wq   = (const float*)d_in[1];
    const float* Wk   = (const float*)d_in[2];
    const float* Wv   = (const float*)d_in[3];
    const float* Wo   = (const float*)d_in[4];
    const float* Wb   = (const float*)d_in[5];
    const float* rmsw = (const float*)d_in[6];
    float* outp = (float*)d_out;

    // one-shot bf16 hi/lo splits
    split_w_kernel<<<dim3(DM * DM / 4 / 256, 4), 256>>>(Wq, Wk, Wv, Wo);
    split_x_kernel<<<MROWS * DM / 4 / 256, 256>>>(x);

    // projections: fused SiLU + l2norm(q,k) on tensor cores (bf16x3)
    mma_qkv<<<dim3(DM / 128, MROWS / 128, 3), 256>>>();
    beta_kernel<<<MROWS, 512>>>(x, Wb);

    // sequential delta-rule recurrence (64 independent states)
    recurrence_kernel<<<BB * NH, 256>>>();

    // rmsnorm fused into attn split, then output projection
    row_rms_kernel<<<MROWS, 256>>>();
    split_attn_kernel<<<MROWS * DM / 4 / 256, 256>>>(rmsw);
    mma_o<<<dim3(DM / 128, MROWS / 128), 256>>>(outp);
}